// round 8
// baseline (speedup 1.0000x reference)
#include <cuda_runtime.h>
#include <cuda_bf16.h>
#include <math.h>
#include <stdint.h>

#define BATCH 2
#define SEQ   2048
#define CH    1024
#define NHEAD 16
#define HD    64
#define MROWS (BATCH*SEQ)   // 4096

// ---------------------------------------------------------------------------
// scratch (device globals; allocation forbidden)
// ---------------------------------------------------------------------------
__device__ __nv_bfloat16 g_xhi[MROWS*CH];
__device__ __nv_bfloat16 g_xlo[MROWS*CH];
__device__ __nv_bfloat16 g_qhi[MROWS*CH];
__device__ __nv_bfloat16 g_qlo[MROWS*CH];
__device__ __nv_bfloat16 g_khi[MROWS*CH];
__device__ __nv_bfloat16 g_klo[MROWS*CH];
__device__ __nv_bfloat16 g_vhi[MROWS*CH];
__device__ __nv_bfloat16 g_vlo[MROWS*CH];
__device__ __nv_bfloat16 g_wthi[4*CH*CH];
__device__ __nv_bfloat16 g_wtlo[4*CH*CH];

// ---------------------------------------------------------------------------
// helpers
// ---------------------------------------------------------------------------
__device__ __forceinline__ uint32_t smem_u32(const void* p) {
    uint32_t a;
    asm("{ .reg .u64 t; cvta.to.shared.u64 t, %1; cvt.u32.u64 %0, t; }"
        : "=r"(a) : "l"(p));
    return a;
}

__device__ __forceinline__ void mma16816(float c[4],
                                         uint32_t a0, uint32_t a1,
                                         uint32_t a2, uint32_t a3,
                                         uint32_t b0, uint32_t b1)
{
    asm volatile(
        "mma.sync.aligned.m16n8k16.row.col.f32.bf16.bf16.f32 "
        "{%0,%1,%2,%3}, {%4,%5,%6,%7}, {%8,%9}, {%0,%1,%2,%3};"
        : "+f"(c[0]), "+f"(c[1]), "+f"(c[2]), "+f"(c[3])
        : "r"(a0), "r"(a1), "r"(a2), "r"(a3), "r"(b0), "r"(b1));
}

#define LDSM_X4(r0,r1,r2,r3,a) \
    asm volatile("ldmatrix.sync.aligned.m8n8.x4.shared.b16 {%0,%1,%2,%3}, [%4];" \
        : "=r"(r0), "=r"(r1), "=r"(r2), "=r"(r3) : "r"(a))
#define LDSM_X4_T(r0,r1,r2,r3,a) \
    asm volatile("ldmatrix.sync.aligned.m8n8.x4.trans.shared.b16 {%0,%1,%2,%3}, [%4];" \
        : "=r"(r0), "=r"(r1), "=r"(r2), "=r"(r3) : "r"(a))

#define CP16(dst_u32, src) \
    asm volatile("cp.async.ca.shared.global [%0], [%1], 16;" \
        :: "r"(dst_u32), "l"(src) : "memory")
#define CP_COMMIT() asm volatile("cp.async.commit_group;" ::: "memory")
#define CP_WAIT0()  asm volatile("cp.async.wait_group 0;"  ::: "memory")

__device__ __forceinline__ void split2(float x, float y, uint32_t& hi, uint32_t& lo)
{
    __nv_bfloat16 hx = __float2bfloat16(x);
    __nv_bfloat16 hy = __float2bfloat16(y);
    __nv_bfloat16 lx = __float2bfloat16(x - __bfloat162float(hx));
    __nv_bfloat16 ly = __float2bfloat16(y - __bfloat162float(hy));
    __nv_bfloat162 hv(hx, hy), lv(lx, ly);
    hi = *(uint32_t*)&hv;
    lo = *(uint32_t*)&lv;
}

// ---------------------------------------------------------------------------
// fp32 -> bf16 hi/lo elementwise split
// ---------------------------------------------------------------------------
__global__ void split_kernel(const float* __restrict__ x,
                             __nv_bfloat16* __restrict__ hi,
                             __nv_bfloat16* __restrict__ lo, int n4)
{
    int i = blockIdx.x * blockDim.x + threadIdx.x;
    if (i >= n4) return;
    float4 v = ((const float4*)x)[i];
    float f[4] = {v.x, v.y, v.z, v.w};
    __nv_bfloat16 h[4], l[4];
#pragma unroll
    for (int u = 0; u < 4; u++) {
        h[u] = __float2bfloat16(f[u]);
        l[u] = __float2bfloat16(f[u] - __bfloat162float(h[u]));
    }
    ((uint2*)hi)[i] = *(uint2*)h;
    ((uint2*)lo)[i] = *(uint2*)l;
}

// ---------------------------------------------------------------------------
// W [K,N] fp32 -> W^T [N,K] bf16 hi/lo; grid.z selects which of 4 weights
// ---------------------------------------------------------------------------
struct TArgs { const float* W[4]; __nv_bfloat16* Th[4]; __nv_bfloat16* Tl[4]; };

__global__ void transpose_split_kernel(TArgs ta)
{
    __shared__ float t[32][33];
    const float* W = ta.W[blockIdx.z];
    __nv_bfloat16* Thi = ta.Th[blockIdx.z];
    __nv_bfloat16* Tlo = ta.Tl[blockIdx.z];
    const int kk = blockIdx.y * 32;
    const int nn = blockIdx.x * 32;
    const int tx = threadIdx.x, ty = threadIdx.y;
#pragma unroll
    for (int j = 0; j < 4; j++)
        t[ty + j * 8][tx] = W[(size_t)(kk + ty + j * 8) * CH + nn + tx];
    __syncthreads();
#pragma unroll
    for (int j = 0; j < 4; j++) {
        float v = t[tx][ty + j * 8];
        __nv_bfloat16 h = __float2bfloat16(v);
        __nv_bfloat16 l = __float2bfloat16(v - __bfloat162float(h));
        size_t o = (size_t)(nn + ty + j * 8) * CH + kk + tx;
        Thi[o] = h;
        Tlo[o] = l;
    }
}

// ---------------------------------------------------------------------------
// GEMM: out = (Ahi+Alo)[M,K] @ (Bhi+Blo)[N,K]^T + bias  (bf16x3 on HMMA)
// CTA 128x128, 8 warps (2x4), K-chunk 64, 2-stage cp.async pipeline.
// One barrier + one wait per 192-MMA chunk.
// ---------------------------------------------------------------------------
#define PITCH 72
#define G_ARR (128*PITCH*2)       // bytes per array (18432)
#define G_STG (4*G_ARR)           // bytes per stage (73728)

struct GemmArgs {
    const __nv_bfloat16* Bh[3];
    const __nv_bfloat16* Bl[3];
    const float* bias[3];
    float* outf[3];
    __nv_bfloat16* oh[3];
    __nv_bfloat16* ol[3];
};

__global__ void __launch_bounds__(256)
gemm_mma_bf16x3(const __nv_bfloat16* __restrict__ Ahi,
                const __nv_bfloat16* __restrict__ Alo,
                GemmArgs ga, int K, int N)
{
    extern __shared__ __nv_bfloat16 sm[];
    const uint32_t ub = smem_u32(sm);

    const int z = blockIdx.z;
    const __nv_bfloat16* Bhi = ga.Bh[z];
    const __nv_bfloat16* Blo = ga.Bl[z];

    const int tid  = threadIdx.x;
    const int warp = tid >> 5;
    const int lane = tid & 31;
    const int grp  = lane >> 2;
    const int tig  = lane & 3;
    const int wm   = warp >> 2;
    const int wn   = warp & 3;
    const int m0 = blockIdx.y * 128;
    const int n0 = blockIdx.x * 128;

    float c[4][4][4];
#pragma unroll
    for (int mt = 0; mt < 4; mt++)
#pragma unroll
        for (int nt = 0; nt < 4; nt++)
#pragma unroll
            for (int f = 0; f < 4; f++) c[mt][nt][f] = 0.f;

    const int row = tid >> 3;          // 0..31
    const int cg  = tid & 7;
    const uint32_t so_b = (uint32_t)(row * PITCH + cg * 8) * 2;
    const size_t   go_a = (size_t)(m0 + row) * K + cg * 8;
    const size_t   go_b = (size_t)(n0 + row) * K + cg * 8;

#define GEMM_LOAD(k0, sbase) do {                                          \
    _Pragma("unroll")                                                      \
    for (int i_ = 0; i_ < 4; i_++) {                                       \
        uint32_t d_ = (sbase) + so_b + (uint32_t)(i_ * 32 * PITCH * 2);    \
        size_t ga_ = go_a + (size_t)(i_ * 32) * K + (k0);                  \
        size_t gb_ = go_b + (size_t)(i_ * 32) * K + (k0);                  \
        CP16(d_ + 0u * G_ARR, Ahi + ga_);                                  \
        CP16(d_ + 1u * G_ARR, Alo + ga_);                                  \
        CP16(d_ + 2u * G_ARR, Bhi + gb_);                                  \
        CP16(d_ + 3u * G_ARR, Blo + gb_);                                  \
    }                                                                      \
} while (0)

    const int nc = K / 64;
    GEMM_LOAD(0, ub);
    CP_COMMIT();

    for (int ch = 0; ch < nc; ch++) {
        CP_WAIT0();
        __syncthreads();
        if (ch + 1 < nc) {
            GEMM_LOAD((ch + 1) * 64, ub + (uint32_t)(((ch + 1) & 1) * G_STG));
            CP_COMMIT();
        }

        const __nv_bfloat16* st = sm + (size_t)(ch & 1) * (G_STG / 2);
        const __nv_bfloat16* sAh = st;
        const __nv_bfloat16* sAl = st + 128 * PITCH;
        const __nv_bfloat16* sBh = st + 2 * 128 * PITCH;
        const __nv_bfloat16* sBl = st + 3 * 128 * PITCH;

#pragma unroll
        for (int ks = 0; ks < 4; ks++) {
            const int kof = ks * 16 + 2 * tig;
            uint32_t bh[4][2], bl[4][2];
#pragma unroll
            for (int nt = 0; nt < 4; nt++) {
                int nrow = wn * 32 + nt * 8 + grp;
                bh[nt][0] = *(const uint32_t*)&sBh[nrow * PITCH + kof];
                bh[nt][1] = *(const uint32_t*)&sBh[nrow * PITCH + kof + 8];
                bl[nt][0] = *(const uint32_t*)&sBl[nrow * PITCH + kof];
                bl[nt][1] = *(const uint32_t*)&sBl[nrow * PITCH + kof + 8];
            }
#pragma unroll
            for (int mt = 0; mt < 4; mt++) {
                int mrow = wm * 64 + mt * 16 + grp;
                uint32_t ah0 = *(const uint32_t*)&sAh[mrow * PITCH + kof];
                uint32_t ah1 = *(const uint32_t*)&sAh[(mrow + 8) * PITCH + kof];
                uint32_t ah2 = *(const uint32_t*)&sAh[mrow * PITCH + kof + 8];
                uint32_t ah3 = *(const uint32_t*)&sAh[(mrow + 8) * PITCH + kof + 8];
                uint32_t al0 = *(const uint32_t*)&sAl[mrow * PITCH + kof];
                uint32_t al1 = *(const uint32_t*)&sAl[(mrow + 8) * PITCH + kof];
                uint32_t al2 = *(const uint32_t*)&sAl[mrow * PITCH + kof + 8];
                uint32_t al3 = *(const uint32_t*)&sAl[(mrow + 8) * PITCH + kof + 8];
#pragma unroll
                for (int nt = 0; nt < 4; nt++) {
                    mma16816(c[mt][nt], ah0, ah1, ah2, ah3, bh[nt][0], bh[nt][1]);
                    mma16816(c[mt][nt], ah0, ah1, ah2, ah3, bl[nt][0], bl[nt][1]);
                    mma16816(c[mt][nt], al0, al1, al2, al3, bh[nt][0], bh[nt][1]);
                }
            }
        }
    }

    const float* bias = ga.bias[z];
    float* outf = ga.outf[z];
    __nv_bfloat16* oh = ga.oh[z];
    __nv_bfloat16* ol = ga.ol[z];
#pragma unroll
    for (int mt = 0; mt < 4; mt++) {
        int r0 = m0 + wm * 64 + mt * 16 + grp;
#pragma unroll
        for (int nt = 0; nt < 4; nt++) {
            int col = n0 + wn * 32 + nt * 8 + 2 * tig;
            float2 bv = *(const float2*)(bias + col);
            float v00 = c[mt][nt][0] + bv.x, v01 = c[mt][nt][1] + bv.y;
            float v10 = c[mt][nt][2] + bv.x, v11 = c[mt][nt][3] + bv.y;
            if (outf) {
                *(float2*)(outf + (size_t)r0 * N + col) = make_float2(v00, v01);
                *(float2*)(outf + (size_t)(r0 + 8) * N + col) = make_float2(v10, v11);
            } else {
                uint32_t h0, l0, h1, l1;
                split2(v00, v01, h0, l0);
                split2(v10, v11, h1, l1);
                *(uint32_t*)(oh + (size_t)r0 * N + col) = h0;
                *(uint32_t*)(ol + (size_t)r0 * N + col) = l0;
                *(uint32_t*)(oh + (size_t)(r0 + 8) * N + col) = h1;
                *(uint32_t*)(ol + (size_t)(r0 + 8) * N + col) = l1;
            }
        }
    }
}

// ---------------------------------------------------------------------------
// HMMA flash attention (swapped roles), ldmatrix + 2-stage cp.async K/V.
// Br=Bc=64, 4 warps. Q resident; K/V tiles double-buffered.
// ---------------------------------------------------------------------------
#define AP 72
#define A_ARR (64*AP*2)           // bytes per array (9216)
#define A_QB  (2*A_ARR)           // Q hi+lo (18432)
#define A_STG (4*A_ARR)           // K/V stage: Kh,Kl,Vh,Vl (36864)

__global__ void __launch_bounds__(128)
attn_mma(const __nv_bfloat16* __restrict__ qhi, const __nv_bfloat16* __restrict__ qlo,
         const __nv_bfloat16* __restrict__ khi, const __nv_bfloat16* __restrict__ klo,
         const __nv_bfloat16* __restrict__ vhi, const __nv_bfloat16* __restrict__ vlo,
         __nv_bfloat16* __restrict__ ohi, __nv_bfloat16* __restrict__ olo)
{
    extern __shared__ __nv_bfloat16 sa[];
    __nv_bfloat16* sQh = sa;
    __nv_bfloat16* sQl = sa + 64 * AP;
    const uint32_t ub = smem_u32(sa);

    const int tid  = threadIdx.x;
    const int warp = tid >> 5;
    const int lane = tid & 31;
    const int g    = lane >> 2;
    const int tig  = lane & 3;

    const int i0 = (gridDim.x - 1 - blockIdx.x) * 64;   // heavy tiles first
    const int bh = blockIdx.y;
    const int b  = bh >> 4;
    const int h  = bh & 15;
    const size_t base = (size_t)b * SEQ * CH + (size_t)h * HD;

    const uint32_t qoff = ((warp * 16 + (lane & 15)) * AP + ((lane >> 4) << 3)) * 2;
    const uint32_t koff = (((((lane >> 4) << 3) + (lane & 7)) * AP) + (((lane >> 3) & 1) << 3)) * 2;
    const uint32_t voff = (((((lane >> 3) & 1) << 3) + (lane & 7)) * AP + ((lane >> 4) << 3)) * 2;

    const int lrow = tid >> 3;        // 0..15
    const int lcg  = tid & 7;
    const uint32_t lso = (uint32_t)(lrow * AP + lcg * 8) * 2;

#define ATTN_LOAD(j0, sbase) do {                                           \
    _Pragma("unroll")                                                       \
    for (int i_ = 0; i_ < 4; i_++) {                                        \
        uint32_t d_ = (sbase) + lso + (uint32_t)(i_ * 16 * AP * 2);         \
        size_t go_ = base + (size_t)((j0) + lrow + i_ * 16) * CH + lcg * 8; \
        CP16(d_ + 0u * A_ARR, qhi + go_);                                   \
        CP16(d_ + 1u * A_ARR, qlo + go_);                                   \
        CP16(d_ + 2u * A_ARR, vhi + go_);                                   \
        CP16(d_ + 3u * A_ARR, vlo + go_);                                   \
    }                                                                       \
} while (0)

    // Q tile (= k rows) resident, plain stores
    {
#pragma unroll
        for (int i = 0; i < 4; i++) {
            int rr = lrow + i * 16;
            size_t go = base + (size_t)(i0 + rr) * CH + lcg * 8;
            *(uint4*)&sQh[rr * AP + lcg * 8] = *(const uint4*)(khi + go);
            *(uint4*)&sQl[rr * AP + lcg * 8] = *(const uint4*)(klo + go);
        }
    }
    // prefetch first K/V tile
    ATTN_LOAD(0, ub + A_QB);
    CP_COMMIT();

    float acc[8][4];
#pragma unroll
    for (int nd = 0; nd < 8; nd++)
#pragma unroll
        for (int f = 0; f < 4; f++) acc[nd][f] = 0.f;
    float m0r = -INFINITY, m1r = -INFINITY, l0r = 0.f, l1r = 0.f;

    const float scl = 0.125f * 1.44269504f;
    const int ig0 = i0 + warp * 16 + g;
    const int ig1 = ig0 + 8;

    for (int j0 = 0; j0 <= i0; j0 += 64) {
        const int s = (j0 >> 6) & 1;
        CP_WAIT0();
        __syncthreads();
        if (j0 + 64 <= i0) {
            ATTN_LOAD(j0 + 64, ub + A_QB + (uint32_t)((s ^ 1) * A_STG));
            CP_COMMIT();
        }

        const uint32_t stg = ub + A_QB + (uint32_t)(s * A_STG);
        const uint32_t uKh = stg;
        const uint32_t uKl = stg + 1u * A_ARR;
        const uint32_t uVh = stg + 2u * A_ARR;
        const uint32_t uVl = stg + 3u * A_ARR;

        float sf[8][4];
#pragma unroll
        for (int nt = 0; nt < 8; nt++)
#pragma unroll
            for (int f = 0; f < 4; f++) sf[nt][f] = 0.f;

#pragma unroll
        for (int kd = 0; kd < 4; kd++) {
            uint32_t ah0, ah1, ah2, ah3, al0, al1, al2, al3;
            LDSM_X4(ah0, ah1, ah2, ah3, ub + qoff + kd * 32);
            LDSM_X4(al0, al1, al2, al3, ub + A_ARR + qoff + kd * 32);
#pragma unroll
            for (int ntp = 0; ntp < 4; ntp++) {
                const int nt = ntp * 2;
                const uint32_t off = koff + nt * (8 * AP * 2) + kd * 32;
                uint32_t kh0, kh1, kh2, kh3, kl0, kl1, kl2, kl3;
                LDSM_X4(kh0, kh1, kh2, kh3, uKh + off);
                LDSM_X4(kl0, kl1, kl2, kl3, uKl + off);
                mma16816(sf[nt],     ah0, ah1, ah2, ah3, kh0, kh1);
                mma16816(sf[nt],     ah0, ah1, ah2, ah3, kl0, kl1);
                mma16816(sf[nt],     al0, al1, al2, al3, kh0, kh1);
                mma16816(sf[nt + 1], ah0, ah1, ah2, ah3, kh2, kh3);
                mma16816(sf[nt + 1], ah0, ah1, ah2, ah3, kl2, kl3);
                mma16816(sf[nt + 1], al0, al1, al2, al3, kh2, kh3);
            }
        }

        if (j0 == i0) {
#pragma unroll
            for (int nt = 0; nt < 8; nt++)
#pragma unroll
                for (int cc = 0; cc < 2; cc++) {
                    int jg = j0 + nt * 8 + 2 * tig + cc;
                    sf[nt][cc]     = (jg <= ig0) ? sf[nt][cc] * scl     : -INFINITY;
                    sf[nt][2 + cc] = (jg <= ig1) ? sf[nt][2 + cc] * scl : -INFINITY;
                }
        } else {
#pragma unroll
            for (int nt = 0; nt < 8; nt++)
#pragma unroll
                for (int f = 0; f < 4; f++) sf[nt][f] *= scl;
        }

        float mx0 = -INFINITY, mx1 = -INFINITY;
#pragma unroll
        for (int nt = 0; nt < 8; nt++) {
            mx0 = fmaxf(mx0, fmaxf(sf[nt][0], sf[nt][1]));
            mx1 = fmaxf(mx1, fmaxf(sf[nt][2], sf[nt][3]));
        }
        mx0 = fmaxf(mx0, __shfl_xor_sync(0xffffffffu, mx0, 1));
        mx0 = fmaxf(mx0, __shfl_xor_sync(0xffffffffu, mx0, 2));
        mx1 = fmaxf(mx1, __shfl_xor_sync(0xffffffffu, mx1, 1));
        mx1 = fmaxf(mx1, __shfl_xor_sync(0xffffffffu, mx1, 2));

        float mn0 = fmaxf(m0r, mx0), mn1 = fmaxf(m1r, mx1);
        float a0f = exp2f(m0r - mn0), a1f = exp2f(m1r - mn1);
        m0r = mn0; m1r = mn1;

        float ps0 = 0.f, ps1 = 0.f;
#pragma unroll
        for (int nt = 0; nt < 8; nt++) {
            sf[nt][0] = exp2f(sf[nt][0] - mn0);
            sf[nt][1] = exp2f(sf[nt][1] - mn0);
            sf[nt][2] = exp2f(sf[nt][2] - mn1);
            sf[nt][3] = exp2f(sf[nt][3] - mn1);
            ps0 += sf[nt][0] + sf[nt][1];
            ps1 += sf[nt][2] + sf[nt][3];
        }
        ps0 += __shfl_xor_sync(0xffffffffu, ps0, 1);
        ps0 += __shfl_xor_sync(0xffffffffu, ps0, 2);
        ps1 += __shfl_xor_sync(0xffffffffu, ps1, 1);
        ps1 += __shfl_xor_sync(0xffffffffu, ps1, 2);
        l0r = l0r * a0f + ps0;
        l1r = l1r * a1f + ps1;

#pragma unroll
        for (int nd = 0; nd < 8; nd++) {
            acc[nd][0] *= a0f; acc[nd][1] *= a0f;
            acc[nd][2] *= a1f; acc[nd][3] *= a1f;
        }

#pragma unroll
        for (int ks = 0; ks < 4; ks++) {
            uint32_t ph0, pl0, ph1, pl1, ph2, pl2, ph3, pl3;
            split2(sf[2 * ks][0],     sf[2 * ks][1],     ph0, pl0);
            split2(sf[2 * ks][2],     sf[2 * ks][3],     ph1, pl1);
            split2(sf[2 * ks + 1][0], sf[2 * ks + 1][1], ph2, pl2);
            split2(sf[2 * ks + 1][2], sf[2 * ks + 1][3], ph3, pl3);
#pragma unroll
            for (int ndp = 0; ndp < 4; ndp++) {
                const int nd = ndp * 2;
                const uint32_t off = voff + ks * (16 * AP * 2) + nd * 16;
                uint32_t vh0, vh1, vh2, vh3, vl0, vl1, vl2, vl3;
                LDSM_X4_T(vh0, vh1, vh2, vh3, uVh + off);
                LDSM_X4_T(vl0, vl1, vl2, vl3, uVl + off);
                mma16816(acc[nd],     ph0, ph1, ph2, ph3, vh0, vh1);
                mma16816(acc[nd],     ph0, ph1, ph2, ph3, vl0, vl1);
                mma16816(acc[nd],     pl0, pl1, pl2, pl3, vh0, vh1);
                mma16816(acc[nd + 1], ph0, ph1, ph2, ph3, vh2, vh3);
                mma16816(acc[nd + 1], ph0, ph1, ph2, ph3, vl2, vl3);
                mma16816(acc[nd + 1], pl0, pl1, pl2, pl3, vh2, vh3);
            }
        }
    }

    const float inv0 = 1.f / l0r, inv1 = 1.f / l1r;
    const size_t r0o = base + (size_t)ig0 * CH;
    const size_t r1o = base + (size_t)ig1 * CH;
#pragma unroll
    for (int nd = 0; nd < 8; nd++) {
        int col = nd * 8 + 2 * tig;
        uint32_t h0, l0, h1, l1;
        split2(acc[nd][0] * inv0, acc[nd][1] * inv0, h0, l0);
        split2(acc[nd][2] * inv1, acc[nd][3] * inv1, h1, l1);
        *(uint32_t*)(ohi + r0o + col) = h0;
        *(uint32_t*)(olo + r0o + col) = l0;
        *(uint32_t*)(ohi + r1o + col) = h1;
        *(uint32_t*)(olo + r1o + col) = l1;
    }
}

// ---------------------------------------------------------------------------
extern "C" void kernel_launch(void* const* d_in, const int* in_sizes, int n_in,
                              void* d_out, int out_size)
{
    const float* x  = (const float*)d_in[0];
    const float* Wq = (const float*)d_in[1];
    const float* bq = (const float*)d_in[2];
    const float* Wk = (const float*)d_in[3];
    const float* bk = (const float*)d_in[4];
    const float* Wv = (const float*)d_in[5];
    const float* bv = (const float*)d_in[6];
    const float* Wp = (const float*)d_in[7];
    const float* bp = (const float*)d_in[8];
    float* out = (float*)d_out;

    __nv_bfloat16 *xhi, *xlo, *qhi, *qlo, *khi, *klo, *vhi, *vlo, *wthi, *wtlo;
    cudaGetSymbolAddress((void**)&xhi,  g_xhi);
    cudaGetSymbolAddress((void**)&xlo,  g_xlo);
    cudaGetSymbolAddress((void**)&qhi,  g_qhi);
    cudaGetSymbolAddress((void**)&qlo,  g_qlo);
    cudaGetSymbolAddress((void**)&khi,  g_khi);
    cudaGetSymbolAddress((void**)&klo,  g_klo);
    cudaGetSymbolAddress((void**)&vhi,  g_vhi);
    cudaGetSymbolAddress((void**)&vlo,  g_vlo);
    cudaGetSymbolAddress((void**)&wthi, g_wthi);
    cudaGetSymbolAddress((void**)&wtlo, g_wtlo);

    const int gemm_smem = 2 * G_STG;                 // 147456
    const int attn_smem = A_QB + 2 * A_STG;          // 92160
    cudaFuncSetAttribute(gemm_mma_bf16x3, cudaFuncAttributeMaxDynamicSharedMemorySize, gemm_smem);
    cudaFuncSetAttribute(attn_mma, cudaFuncAttributeMaxDynamicSharedMemorySize, attn_smem);

    TArgs ta;
    ta.W[0] = Wq; ta.W[1] = Wk; ta.W[2] = Wv; ta.W[3] = Wp;
    for (int i = 0; i < 4; i++) { ta.Th[i] = wthi + (size_t)i * CH * CH;
                                  ta.Tl[i] = wtlo + (size_t)i * CH * CH; }
    transpose_split_kernel<<<dim3(CH / 32, CH / 32, 4), dim3(32, 8)>>>(ta);

    split_kernel<<<MROWS * CH / (256 * 4), 256>>>(x, xhi, xlo, MROWS * CH / 4);

    GemmArgs gq = {};
    gq.Bh[0] = wthi; gq.Bh[1] = wthi + CH * CH; gq.Bh[2] = wthi + 2 * CH * CH;
    gq.Bl[0] = wtlo; gq.Bl[1] = wtlo + CH * CH; gq.Bl[2] = wtlo + 2 * CH * CH;
    gq.bias[0] = bq; gq.bias[1] = bk; gq.bias[2] = bv;
    gq.outf[0] = gq.outf[1] = gq.outf[2] = nullptr;
    gq.oh[0] = qhi; gq.oh[1] = khi; gq.oh[2] = vhi;
    gq.ol[0] = qlo; gq.ol[1] = klo; gq.ol[2] = vlo;
    gemm_mma_bf16x3<<<dim3(CH / 128, MROWS / 128, 3), 256, gemm_smem>>>(xhi, xlo, gq, CH, CH);

    attn_mma<<<dim3(SEQ / 64, BATCH * NHEAD), 128, attn_smem>>>(qhi, qlo, khi, klo, vhi, vlo,
                                                                xhi, xlo);

    GemmArgs gp = {};
    gp.Bh[0] = wthi + 3 * CH * CH;
    gp.Bl[0] = wtlo + 3 * CH * CH;
    gp.bias[0] = bp;
    gp.outf[0] = out;
    gemm_mma_bf16x3<<<dim3(CH / 128, MROWS / 128, 1), 256, gemm_smem>>>(xhi, xlo, gp, CH, CH);
}

// round 9
// speedup vs baseline: 1.0435x; 1.0435x over previous
#include <cuda_runtime.h>
#include <cuda_bf16.h>
#include <math.h>
#include <stdint.h>

#define BATCH 2
#define SEQ   2048
#define CH    1024
#define NHEAD 16
#define HD    64
#define MROWS (BATCH*SEQ)   // 4096

// ---------------------------------------------------------------------------
// scratch (device globals; allocation forbidden)
// ---------------------------------------------------------------------------
__device__ __nv_bfloat16 g_xhi[MROWS*CH];
__device__ __nv_bfloat16 g_xlo[MROWS*CH];
__device__ __nv_bfloat16 g_qhi[MROWS*CH];
__device__ __nv_bfloat16 g_qlo[MROWS*CH];
__device__ __nv_bfloat16 g_khi[MROWS*CH];
__device__ __nv_bfloat16 g_klo[MROWS*CH];
__device__ __nv_bfloat16 g_vhi[MROWS*CH];
__device__ __nv_bfloat16 g_vlo[MROWS*CH];
__device__ __nv_bfloat16 g_wthi[4*CH*CH];
__device__ __nv_bfloat16 g_wtlo[4*CH*CH];

// ---------------------------------------------------------------------------
// helpers
// ---------------------------------------------------------------------------
__device__ __forceinline__ uint32_t smem_u32(const void* p) {
    uint32_t a;
    asm("{ .reg .u64 t; cvta.to.shared.u64 t, %1; cvt.u32.u64 %0, t; }"
        : "=r"(a) : "l"(p));
    return a;
}

__device__ __forceinline__ void mma16816(float c[4],
                                         uint32_t a0, uint32_t a1,
                                         uint32_t a2, uint32_t a3,
                                         uint32_t b0, uint32_t b1)
{
    asm volatile(
        "mma.sync.aligned.m16n8k16.row.col.f32.bf16.bf16.f32 "
        "{%0,%1,%2,%3}, {%4,%5,%6,%7}, {%8,%9}, {%0,%1,%2,%3};"
        : "+f"(c[0]), "+f"(c[1]), "+f"(c[2]), "+f"(c[3])
        : "r"(a0), "r"(a1), "r"(a2), "r"(a3), "r"(b0), "r"(b1));
}

#define LDSM_X4(r0,r1,r2,r3,a) \
    asm volatile("ldmatrix.sync.aligned.m8n8.x4.shared.b16 {%0,%1,%2,%3}, [%4];" \
        : "=r"(r0), "=r"(r1), "=r"(r2), "=r"(r3) : "r"(a))
#define LDSM_X4_T(r0,r1,r2,r3,a) \
    asm volatile("ldmatrix.sync.aligned.m8n8.x4.trans.shared.b16 {%0,%1,%2,%3}, [%4];" \
        : "=r"(r0), "=r"(r1), "=r"(r2), "=r"(r3) : "r"(a))

#define CP16(dst_u32, src) \
    asm volatile("cp.async.ca.shared.global [%0], [%1], 16;" \
        :: "r"(dst_u32), "l"(src) : "memory")
#define CP_COMMIT() asm volatile("cp.async.commit_group;" ::: "memory")
#define CP_WAIT0()  asm volatile("cp.async.wait_group 0;"  ::: "memory")

__device__ __forceinline__ void split2(float x, float y, uint32_t& hi, uint32_t& lo)
{
    __nv_bfloat16 hx = __float2bfloat16(x);
    __nv_bfloat16 hy = __float2bfloat16(y);
    __nv_bfloat16 lx = __float2bfloat16(x - __bfloat162float(hx));
    __nv_bfloat16 ly = __float2bfloat16(y - __bfloat162float(hy));
    __nv_bfloat162 hv(hx, hy), lv(lx, ly);
    hi = *(uint32_t*)&hv;
    lo = *(uint32_t*)&lv;
}

// ---------------------------------------------------------------------------
// fp32 -> bf16 hi/lo elementwise split
// ---------------------------------------------------------------------------
__global__ void split_kernel(const float* __restrict__ x,
                             __nv_bfloat16* __restrict__ hi,
                             __nv_bfloat16* __restrict__ lo, int n4)
{
    int i = blockIdx.x * blockDim.x + threadIdx.x;
    if (i >= n4) return;
    float4 v = ((const float4*)x)[i];
    float f[4] = {v.x, v.y, v.z, v.w};
    __nv_bfloat16 h[4], l[4];
#pragma unroll
    for (int u = 0; u < 4; u++) {
        h[u] = __float2bfloat16(f[u]);
        l[u] = __float2bfloat16(f[u] - __bfloat162float(h[u]));
    }
    ((uint2*)hi)[i] = *(uint2*)h;
    ((uint2*)lo)[i] = *(uint2*)l;
}

// ---------------------------------------------------------------------------
// W [K,N] fp32 -> W^T [N,K] bf16 hi/lo; grid.z selects which of 4 weights
// ---------------------------------------------------------------------------
struct TArgs { const float* W[4]; __nv_bfloat16* Th[4]; __nv_bfloat16* Tl[4]; };

__global__ void transpose_split_kernel(TArgs ta)
{
    __shared__ float t[32][33];
    const float* W = ta.W[blockIdx.z];
    __nv_bfloat16* Thi = ta.Th[blockIdx.z];
    __nv_bfloat16* Tlo = ta.Tl[blockIdx.z];
    const int kk = blockIdx.y * 32;
    const int nn = blockIdx.x * 32;
    const int tx = threadIdx.x, ty = threadIdx.y;
#pragma unroll
    for (int j = 0; j < 4; j++)
        t[ty + j * 8][tx] = W[(size_t)(kk + ty + j * 8) * CH + nn + tx];
    __syncthreads();
#pragma unroll
    for (int j = 0; j < 4; j++) {
        float v = t[tx][ty + j * 8];
        __nv_bfloat16 h = __float2bfloat16(v);
        __nv_bfloat16 l = __float2bfloat16(v - __bfloat162float(h));
        size_t o = (size_t)(nn + ty + j * 8) * CH + kk + tx;
        Thi[o] = h;
        Tlo[o] = l;
    }
}

// ---------------------------------------------------------------------------
// GEMM: out = (Ahi+Alo)[M,K] @ (Bhi+Blo)[N,K]^T + bias  (bf16x3 on HMMA)
// CTA 128x128, 8 warps (2x4), K-chunk 64, synchronous loads (2 CTA/SM),
// ldmatrix fragment loads: 12 LDSM per 48 MMAs (was 48 scalar LDS).
// ---------------------------------------------------------------------------
#define PITCH 72

struct GemmArgs {
    const __nv_bfloat16* Bh[3];
    const __nv_bfloat16* Bl[3];
    const float* bias[3];
    float* outf[3];
    __nv_bfloat16* oh[3];
    __nv_bfloat16* ol[3];
};

__global__ void __launch_bounds__(256, 2)
gemm_mma_bf16x3(const __nv_bfloat16* __restrict__ Ahi,
                const __nv_bfloat16* __restrict__ Alo,
                GemmArgs ga, int K, int N)
{
    extern __shared__ __nv_bfloat16 sm[];
    __nv_bfloat16* sAh = sm;
    __nv_bfloat16* sAl = sm + 128 * PITCH;
    __nv_bfloat16* sBh = sm + 2 * 128 * PITCH;
    __nv_bfloat16* sBl = sm + 3 * 128 * PITCH;
    const uint32_t ub  = smem_u32(sm);
    const uint32_t uAh = ub;
    const uint32_t uAl = ub + 1u * 128 * PITCH * 2;
    const uint32_t uBh = ub + 2u * 128 * PITCH * 2;
    const uint32_t uBl = ub + 3u * 128 * PITCH * 2;

    const int z = blockIdx.z;
    const __nv_bfloat16* Bhi = ga.Bh[z];
    const __nv_bfloat16* Blo = ga.Bl[z];

    const int tid  = threadIdx.x;
    const int warp = tid >> 5;
    const int lane = tid & 31;
    const int grp  = lane >> 2;
    const int tig  = lane & 3;
    const int wm   = warp >> 2;
    const int wn   = warp & 3;
    const int m0 = blockIdx.y * 128;
    const int n0 = blockIdx.x * 128;

    // ldmatrix lane-address offsets (bytes), same patterns as attention
    // A-frag (row-major m16k16): row = base + (lane&15), colgrp = (lane>>4)*8
    const uint32_t aoff = (((wm * 64 + (lane & 15)) * PITCH) + ((lane >> 4) << 3)) * 2;
    // B-frag (row-major n16k16, x4 spans two n8 tiles):
    // row = base + (lane>>4)*8 + (lane&7), colgrp = ((lane>>3)&1)*8
    const uint32_t boff = (((wn * 32 + ((lane >> 4) << 3) + (lane & 7)) * PITCH)
                           + (((lane >> 3) & 1) << 3)) * 2;

    float c[4][4][4];
#pragma unroll
    for (int mt = 0; mt < 4; mt++)
#pragma unroll
        for (int nt = 0; nt < 4; nt++)
#pragma unroll
            for (int f = 0; f < 4; f++) c[mt][nt][f] = 0.f;

    const int row = tid >> 3;
    const int cg  = tid & 7;

    for (int k0 = 0; k0 < K; k0 += 64) {
        __syncthreads();
#pragma unroll
        for (int i = 0; i < 4; i++) {
            int r = row + i * 32;
            size_t ga_ = (size_t)(m0 + r) * K + k0 + cg * 8;
            size_t gb_ = (size_t)(n0 + r) * K + k0 + cg * 8;
            int so = r * PITCH + cg * 8;
            *(uint4*)&sAh[so] = *(const uint4*)(Ahi + ga_);
            *(uint4*)&sAl[so] = *(const uint4*)(Alo + ga_);
            *(uint4*)&sBh[so] = *(const uint4*)(Bhi + gb_);
            *(uint4*)&sBl[so] = *(const uint4*)(Blo + gb_);
        }
        __syncthreads();

#pragma unroll
        for (int ks = 0; ks < 4; ks++) {
            // B fragments: 2 LDSM_X4 per array cover all 4 n-tiles
            uint32_t bh[4][2], bl[4][2];
#pragma unroll
            for (int ntp = 0; ntp < 2; ntp++) {
                const uint32_t off = boff + (uint32_t)(ntp * 16 * PITCH * 2) + ks * 32;
                LDSM_X4(bh[2 * ntp][0], bh[2 * ntp][1],
                        bh[2 * ntp + 1][0], bh[2 * ntp + 1][1], uBh + off);
                LDSM_X4(bl[2 * ntp][0], bl[2 * ntp][1],
                        bl[2 * ntp + 1][0], bl[2 * ntp + 1][1], uBl + off);
            }
#pragma unroll
            for (int mt = 0; mt < 4; mt++) {
                const uint32_t off = aoff + (uint32_t)(mt * 16 * PITCH * 2) + ks * 32;
                uint32_t ah0, ah1, ah2, ah3, al0, al1, al2, al3;
                LDSM_X4(ah0, ah1, ah2, ah3, uAh + off);
                LDSM_X4(al0, al1, al2, al3, uAl + off);
#pragma unroll
                for (int nt = 0; nt < 4; nt++) {
                    mma16816(c[mt][nt], ah0, ah1, ah2, ah3, bh[nt][0], bh[nt][1]);
                    mma16816(c[mt][nt], ah0, ah1, ah2, ah3, bl[nt][0], bl[nt][1]);
                    mma16816(c[mt][nt], al0, al1, al2, al3, bh[nt][0], bh[nt][1]);
                }
            }
        }
    }

    const float* bias = ga.bias[z];
    float* outf = ga.outf[z];
    __nv_bfloat16* oh = ga.oh[z];
    __nv_bfloat16* ol = ga.ol[z];
#pragma unroll
    for (int mt = 0; mt < 4; mt++) {
        int r0 = m0 + wm * 64 + mt * 16 + grp;
#pragma unroll
        for (int nt = 0; nt < 4; nt++) {
            int col = n0 + wn * 32 + nt * 8 + 2 * tig;
            float2 bv = *(const float2*)(bias + col);
            float v00 = c[mt][nt][0] + bv.x, v01 = c[mt][nt][1] + bv.y;
            float v10 = c[mt][nt][2] + bv.x, v11 = c[mt][nt][3] + bv.y;
            if (outf) {
                *(float2*)(outf + (size_t)r0 * N + col) = make_float2(v00, v01);
                *(float2*)(outf + (size_t)(r0 + 8) * N + col) = make_float2(v10, v11);
            } else {
                uint32_t h0, l0, h1, l1;
                split2(v00, v01, h0, l0);
                split2(v10, v11, h1, l1);
                *(uint32_t*)(oh + (size_t)r0 * N + col) = h0;
                *(uint32_t*)(ol + (size_t)r0 * N + col) = l0;
                *(uint32_t*)(oh + (size_t)(r0 + 8) * N + col) = h1;
                *(uint32_t*)(ol + (size_t)(r0 + 8) * N + col) = l1;
            }
        }
    }
}

// ---------------------------------------------------------------------------
// HMMA flash attention (swapped roles), ldmatrix + 2-stage cp.async K/V.
// (unchanged from round 8 — measured 187us)
// ---------------------------------------------------------------------------
#define AP 72
#define A_ARR (64*AP*2)
#define A_QB  (2*A_ARR)
#define A_STG (4*A_ARR)

__global__ void __launch_bounds__(128)
attn_mma(const __nv_bfloat16* __restrict__ qhi, const __nv_bfloat16* __restrict__ qlo,
         const __nv_bfloat16* __restrict__ khi, const __nv_bfloat16* __restrict__ klo,
         const __nv_bfloat16* __restrict__ vhi, const __nv_bfloat16* __restrict__ vlo,
         __nv_bfloat16* __restrict__ ohi, __nv_bfloat16* __restrict__ olo)
{
    extern __shared__ __nv_bfloat16 sa[];
    __nv_bfloat16* sQh = sa;
    __nv_bfloat16* sQl = sa + 64 * AP;
    const uint32_t ub = smem_u32(sa);

    const int tid  = threadIdx.x;
    const int warp = tid >> 5;
    const int lane = tid & 31;
    const int g    = lane >> 2;
    const int tig  = lane & 3;

    const int i0 = (gridDim.x - 1 - blockIdx.x) * 64;
    const int bh = blockIdx.y;
    const int b  = bh >> 4;
    const int h  = bh & 15;
    const size_t base = (size_t)b * SEQ * CH + (size_t)h * HD;

    const uint32_t qoff = ((warp * 16 + (lane & 15)) * AP + ((lane >> 4) << 3)) * 2;
    const uint32_t koff = (((((lane >> 4) << 3) + (lane & 7)) * AP) + (((lane >> 3) & 1) << 3)) * 2;
    const uint32_t voff = (((((lane >> 3) & 1) << 3) + (lane & 7)) * AP + ((lane >> 4) << 3)) * 2;

    const int lrow = tid >> 3;
    const int lcg  = tid & 7;
    const uint32_t lso = (uint32_t)(lrow * AP + lcg * 8) * 2;

#define ATTN_LOAD(j0, sbase) do {                                           \
    _Pragma("unroll")                                                       \
    for (int i_ = 0; i_ < 4; i_++) {                                        \
        uint32_t d_ = (sbase) + lso + (uint32_t)(i_ * 16 * AP * 2);         \
        size_t go_ = base + (size_t)((j0) + lrow + i_ * 16) * CH + lcg * 8; \
        CP16(d_ + 0u * A_ARR, qhi + go_);                                   \
        CP16(d_ + 1u * A_ARR, qlo + go_);                                   \
        CP16(d_ + 2u * A_ARR, vhi + go_);                                   \
        CP16(d_ + 3u * A_ARR, vlo + go_);                                   \
    }                                                                       \
} while (0)

    {
#pragma unroll
        for (int i = 0; i < 4; i++) {
            int rr = lrow + i * 16;
            size_t go = base + (size_t)(i0 + rr) * CH + lcg * 8;
            *(uint4*)&sQh[rr * AP + lcg * 8] = *(const uint4*)(khi + go);
            *(uint4*)&sQl[rr * AP + lcg * 8] = *(const uint4*)(klo + go);
        }
    }
    ATTN_LOAD(0, ub + A_QB);
    CP_COMMIT();

    float acc[8][4];
#pragma unroll
    for (int nd = 0; nd < 8; nd++)
#pragma unroll
        for (int f = 0; f < 4; f++) acc[nd][f] = 0.f;
    float m0r = -INFINITY, m1r = -INFINITY, l0r = 0.f, l1r = 0.f;

    const float scl = 0.125f * 1.44269504f;
    const int ig0 = i0 + warp * 16 + g;
    const int ig1 = ig0 + 8;

    for (int j0 = 0; j0 <= i0; j0 += 64) {
        const int s = (j0 >> 6) & 1;
        CP_WAIT0();
        __syncthreads();
        if (j0 + 64 <= i0) {
            ATTN_LOAD(j0 + 64, ub + A_QB + (uint32_t)((s ^ 1) * A_STG));
            CP_COMMIT();
        }

        const uint32_t stg = ub + A_QB + (uint32_t)(s * A_STG);
        const uint32_t uKh = stg;
        const uint32_t uKl = stg + 1u * A_ARR;
        const uint32_t uVh = stg + 2u * A_ARR;
        const uint32_t uVl = stg + 3u * A_ARR;

        float sf[8][4];
#pragma unroll
        for (int nt = 0; nt < 8; nt++)
#pragma unroll
            for (int f = 0; f < 4; f++) sf[nt][f] = 0.f;

#pragma unroll
        for (int kd = 0; kd < 4; kd++) {
            uint32_t ah0, ah1, ah2, ah3, al0, al1, al2, al3;
            LDSM_X4(ah0, ah1, ah2, ah3, ub + qoff + kd * 32);
            LDSM_X4(al0, al1, al2, al3, ub + A_ARR + qoff + kd * 32);
#pragma unroll
            for (int ntp = 0; ntp < 4; ntp++) {
                const int nt = ntp * 2;
                const uint32_t off = koff + nt * (8 * AP * 2) + kd * 32;
                uint32_t kh0, kh1, kh2, kh3, kl0, kl1, kl2, kl3;
                LDSM_X4(kh0, kh1, kh2, kh3, uKh + off);
                LDSM_X4(kl0, kl1, kl2, kl3, uKl + off);
                mma16816(sf[nt],     ah0, ah1, ah2, ah3, kh0, kh1);
                mma16816(sf[nt],     ah0, ah1, ah2, ah3, kl0, kl1);
                mma16816(sf[nt],     al0, al1, al2, al3, kh0, kh1);
                mma16816(sf[nt + 1], ah0, ah1, ah2, ah3, kh2, kh3);
                mma16816(sf[nt + 1], ah0, ah1, ah2, ah3, kl2, kl3);
                mma16816(sf[nt + 1], al0, al1, al2, al3, kh2, kh3);
            }
        }

        if (j0 == i0) {
#pragma unroll
            for (int nt = 0; nt < 8; nt++)
#pragma unroll
                for (int cc = 0; cc < 2; cc++) {
                    int jg = j0 + nt * 8 + 2 * tig + cc;
                    sf[nt][cc]     = (jg <= ig0) ? sf[nt][cc] * scl     : -INFINITY;
                    sf[nt][2 + cc] = (jg <= ig1) ? sf[nt][2 + cc] * scl : -INFINITY;
                }
        } else {
#pragma unroll
            for (int nt = 0; nt < 8; nt++)
#pragma unroll
                for (int f = 0; f < 4; f++) sf[nt][f] *= scl;
        }

        float mx0 = -INFINITY, mx1 = -INFINITY;
#pragma unroll
        for (int nt = 0; nt < 8; nt++) {
            mx0 = fmaxf(mx0, fmaxf(sf[nt][0], sf[nt][1]));
            mx1 = fmaxf(mx1, fmaxf(sf[nt][2], sf[nt][3]));
        }
        mx0 = fmaxf(mx0, __shfl_xor_sync(0xffffffffu, mx0, 1));
        mx0 = fmaxf(mx0, __shfl_xor_sync(0xffffffffu, mx0, 2));
        mx1 = fmaxf(mx1, __shfl_xor_sync(0xffffffffu, mx1, 1));
        mx1 = fmaxf(mx1, __shfl_xor_sync(0xffffffffu, mx1, 2));

        float mn0 = fmaxf(m0r, mx0), mn1 = fmaxf(m1r, mx1);
        float a0f = exp2f(m0r - mn0), a1f = exp2f(m1r - mn1);
        m0r = mn0; m1r = mn1;

        float ps0 = 0.f, ps1 = 0.f;
#pragma unroll
        for (int nt = 0; nt < 8; nt++) {
            sf[nt][0] = exp2f(sf[nt][0] - mn0);
            sf[nt][1] = exp2f(sf[nt][1] - mn0);
            sf[nt][2] = exp2f(sf[nt][2] - mn1);
            sf[nt][3] = exp2f(sf[nt][3] - mn1);
            ps0 += sf[nt][0] + sf[nt][1];
            ps1 += sf[nt][2] + sf[nt][3];
        }
        ps0 += __shfl_xor_sync(0xffffffffu, ps0, 1);
        ps0 += __shfl_xor_sync(0xffffffffu, ps0, 2);
        ps1 += __shfl_xor_sync(0xffffffffu, ps1, 1);
        ps1 += __shfl_xor_sync(0xffffffffu, ps1, 2);
        l0r = l0r * a0f + ps0;
        l1r = l1r * a1f + ps1;

#pragma unroll
        for (int nd = 0; nd < 8; nd++) {
            acc[nd][0] *= a0f; acc[nd][1] *= a0f;
            acc[nd][2] *= a1f; acc[nd][3] *= a1f;
        }

#pragma unroll
        for (int ks = 0; ks < 4; ks++) {
            uint32_t ph0, pl0, ph1, pl1, ph2, pl2, ph3, pl3;
            split2(sf[2 * ks][0],     sf[2 * ks][1],     ph0, pl0);
            split2(sf[2 * ks][2],     sf[2 * ks][3],     ph1, pl1);
            split2(sf[2 * ks + 1][0], sf[2 * ks + 1][1], ph2, pl2);
            split2(sf[2 * ks + 1][2], sf[2 * ks + 1][3], ph3, pl3);
#pragma unroll
            for (int ndp = 0; ndp < 4; ndp++) {
                const int nd = ndp * 2;
                const uint32_t off = voff + ks * (16 * AP * 2) + nd * 16;
                uint32_t vh0, vh1, vh2, vh3, vl0, vl1, vl2, vl3;
                LDSM_X4_T(vh0, vh1, vh2, vh3, uVh + off);
                LDSM_X4_T(vl0, vl1, vl2, vl3, uVl + off);
                mma16816(acc[nd],     ph0, ph1, ph2, ph3, vh0, vh1);
                mma16816(acc[nd],     ph0, ph1, ph2, ph3, vl0, vl1);
                mma16816(acc[nd],     pl0, pl1, pl2, pl3, vh0, vh1);
                mma16816(acc[nd + 1], ph0, ph1, ph2, ph3, vh2, vh3);
                mma16816(acc[nd + 1], ph0, ph1, ph2, ph3, vl2, vl3);
                mma16816(acc[nd + 1], pl0, pl1, pl2, pl3, vh2, vh3);
            }
        }
    }

    const float inv0 = 1.f / l0r, inv1 = 1.f / l1r;
    const size_t r0o = base + (size_t)ig0 * CH;
    const size_t r1o = base + (size_t)ig1 * CH;
#pragma unroll
    for (int nd = 0; nd < 8; nd++) {
        int col = nd * 8 + 2 * tig;
        uint32_t h0, l0, h1, l1;
        split2(acc[nd][0] * inv0, acc[nd][1] * inv0, h0, l0);
        split2(acc[nd][2] * inv1, acc[nd][3] * inv1, h1, l1);
        *(uint32_t*)(ohi + r0o + col) = h0;
        *(uint32_t*)(olo + r0o + col) = l0;
        *(uint32_t*)(ohi + r1o + col) = h1;
        *(uint32_t*)(olo + r1o + col) = l1;
    }
}

// ---------------------------------------------------------------------------
extern "C" void kernel_launch(void* const* d_in, const int* in_sizes, int n_in,
                              void* d_out, int out_size)
{
    const float* x  = (const float*)d_in[0];
    const float* Wq = (const float*)d_in[1];
    const float* bq = (const float*)d_in[2];
    const float* Wk = (const float*)d_in[3];
    const float* bk = (const float*)d_in[4];
    const float* Wv = (const float*)d_in[5];
    const float* bv = (const float*)d_in[6];
    const float* Wp = (const float*)d_in[7];
    const float* bp = (const float*)d_in[8];
    float* out = (float*)d_out;

    __nv_bfloat16 *xhi, *xlo, *qhi, *qlo, *khi, *klo, *vhi, *vlo, *wthi, *wtlo;
    cudaGetSymbolAddress((void**)&xhi,  g_xhi);
    cudaGetSymbolAddress((void**)&xlo,  g_xlo);
    cudaGetSymbolAddress((void**)&qhi,  g_qhi);
    cudaGetSymbolAddress((void**)&qlo,  g_qlo);
    cudaGetSymbolAddress((void**)&khi,  g_khi);
    cudaGetSymbolAddress((void**)&klo,  g_klo);
    cudaGetSymbolAddress((void**)&vhi,  g_vhi);
    cudaGetSymbolAddress((void**)&vlo,  g_vlo);
    cudaGetSymbolAddress((void**)&wthi, g_wthi);
    cudaGetSymbolAddress((void**)&wtlo, g_wtlo);

    const int gemm_smem = 4 * 128 * PITCH * (int)sizeof(__nv_bfloat16);  // 73728
    const int attn_smem = A_QB + 2 * A_STG;                              // 92160
    cudaFuncSetAttribute(gemm_mma_bf16x3, cudaFuncAttributeMaxDynamicSharedMemorySize, gemm_smem);
    cudaFuncSetAttribute(attn_mma, cudaFuncAttributeMaxDynamicSharedMemorySize, attn_smem);

    TArgs ta;
    ta.W[0] = Wq; ta.W[1] = Wk; ta.W[2] = Wv; ta.W[3] = Wp;
    for (int i = 0; i < 4; i++) { ta.Th[i] = wthi + (size_t)i * CH * CH;
                                  ta.Tl[i] = wtlo + (size_t)i * CH * CH; }
    transpose_split_kernel<<<dim3(CH / 32, CH / 32, 4), dim3(32, 8)>>>(ta);

    split_kernel<<<MROWS * CH / (256 * 4), 256>>>(x, xhi, xlo, MROWS * CH / 4);

    GemmArgs gq = {};
    gq.Bh[0] = wthi; gq.Bh[1] = wthi + CH * CH; gq.Bh[2] = wthi + 2 * CH * CH;
    gq.Bl[0] = wtlo; gq.Bl[1] = wtlo + CH * CH; gq.Bl[2] = wtlo + 2 * CH * CH;
    gq.bias[0] = bq; gq.bias[1] = bk; gq.bias[2] = bv;
    gq.outf[0] = gq.outf[1] = gq.outf[2] = nullptr;
    gq.oh[0] = qhi; gq.oh[1] = khi; gq.oh[2] = vhi;
    gq.ol[0] = qlo; gq.ol[1] = klo; gq.ol[2] = vlo;
    gemm_mma_bf16x3<<<dim3(CH / 128, MROWS / 128, 3), 256, gemm_smem>>>(xhi, xlo, gq, CH, CH);

    attn_mma<<<dim3(SEQ / 64, BATCH * NHEAD), 128, attn_smem>>>(qhi, qlo, khi, klo, vhi, vlo,
                                                                xhi, xlo);

    GemmArgs gp = {};
    gp.Bh[0] = wthi + 3 * CH * CH;
    gp.Bl[0] = wtlo + 3 * CH * CH;
    gp.bias[0] = bp;
    gp.outf[0] = out;
    gemm_mma_bf16x3<<<dim3(CH / 128, MROWS / 128, 1), 256, gemm_smem>>>(xhi, xlo, gp, CH, CH);
}